// round 10
// baseline (speedup 1.0000x reference)
#include <cuda_runtime.h>
#include <cuda_bf16.h>
#include <math.h>
#include <float.h>

// Problem constants
#define NB   64          // batch
#define NN   256         // nodes
#define TT   256         // feature dim
#define DD   64          // embedding dim
#define KK   16          // top-k

// Scratch (device globals: no allocation allowed)
__device__ float g_Y[NB * NN * TT];          // 16 MB intermediate Y = A @ x
__device__ float g_EnT[DD * NN];             // normalized emb (transposed)
__device__ int   g_adj[NN * KK];
__device__ float g_w[NN * KK];
__device__ int   g_cnt[NN];

// ---------------------------------------------------------------------------
// Kernel 0: normalized-transposed embedding.
// 1 block x 256 threads. Coalesced LDG staging -> padded smem ->
// per-row norm -> coalesced EnT stores.
// ---------------------------------------------------------------------------
#define PREP_SMEM_BYTES (NN * 65 * 4)

__global__ void prep_emb_kernel(const float* __restrict__ emb)
{
    extern __shared__ float se[];             // [256][65] padded
    const int t = threadIdx.x;

    #pragma unroll
    for (int q = 0; q < 16; q++) {
        int li = q * 256 + t;                 // float4 index
        float4 v = *(const float4*)&emb[li * 4];
        int row = li >> 4;
        int col = (li & 15) * 4;
        se[row * 65 + col + 0] = v.x;
        se[row * 65 + col + 1] = v.y;
        se[row * 65 + col + 2] = v.z;
        se[row * 65 + col + 3] = v.w;
    }
    __syncthreads();

    float ss = 0.f;
    #pragma unroll
    for (int d = 0; d < DD; d++) {
        float a = se[t * 65 + d];
        ss = fmaf(a, a, ss);
    }
    const float rn = rsqrtf(ss);

    #pragma unroll
    for (int d = 0; d < DD; d++) {
        g_EnT[d * NN + t] = se[t * 65 + d] * rn;
    }
}

// ---------------------------------------------------------------------------
// Kernel 1: build gated kNN graph.
// One block per destination node i; 256 threads compute cos (coalesced via
// EnT; row-i norm fused into the dot loop); warp 0 alone does the 16-round
// argmax in registers (no block barriers in the selection loop).
// ---------------------------------------------------------------------------
__global__ void build_graph_kernel(const float* __restrict__ emb,
                                   const float* __restrict__ logits,
                                   const float* __restrict__ gumbel)
{
    const int i    = blockIdx.x;
    const int t    = threadIdx.x;
    const int lane = t & 31;
    const int warp = t >> 5;

    __shared__ float si[DD];      // raw emb row i
    __shared__ float wv[NN];      // cos values
    __shared__ int   sel[KK];
    __shared__ float sgate[KK];

    if (t < DD) si[t] = emb[i * DD + t];      // coalesced: 2 lines
    __syncthreads();

    float dot = 0.f, ss = 0.f;
    #pragma unroll
    for (int d = 0; d < DD; d++) {
        float a = si[d];
        dot = fmaf(a, g_EnT[d * NN + t], dot);
        ss  = fmaf(a, a, ss);
    }
    wv[t] = dot * rsqrtf(ss);
    __syncthreads();

    if (warp == 0) {
        float v[8];
        #pragma unroll
        for (int m = 0; m < 8; m++) v[m] = wv[m * 32 + lane];

        for (int r = 0; r < KK; r++) {
            float bv = v[0];
            int   bm = 0;
            #pragma unroll
            for (int m = 1; m < 8; m++) {
                if (v[m] > bv) { bv = v[m]; bm = m; }   // strict >: keeps lowest m
            }
            int bidx = bm * 32 + lane;
            #pragma unroll
            for (int s = 16; s > 0; s >>= 1) {
                float ov = __shfl_down_sync(0xffffffffu, bv, s);
                int   oi = __shfl_down_sync(0xffffffffu, bidx, s);
                if (ov > bv || (ov == bv && oi < bidx)) { bv = ov; bidx = oi; }
            }
            bidx = __shfl_sync(0xffffffffu, bidx, 0);   // broadcast winner
            if (lane == 0) sel[r] = bidx;
            if ((bidx & 31) == lane) v[bidx >> 5] = -FLT_MAX;  // owner invalidates
        }
        __syncwarp();

        if (lane < KK) {
            int j = sel[lane];
            long idx = (long)i * NN + j;
            float u0 = gumbel[idx * 2 + 0];
            float u1 = gumbel[idx * 2 + 1];
            float g0 = -logf(-logf(u0));
            float g1 = -logf(-logf(u1));
            float v0 = logits[idx * 2 + 0] + g0;
            float v1 = logits[idx * 2 + 1] + g1;
            float m  = fmaxf(v0, v1);
            float e0 = expf(v0 - m), e1 = expf(v1 - m);
            float s0 = e0 / (e0 + e1);
            float hard0 = (v0 >= v1) ? 1.0f : 0.0f;   // argmax ties -> index 0
            float gate = (hard0 + s0) - s0;           // straight-through forward value
            sgate[lane] = gate;
        }
        __syncwarp();

        if (lane == 0) {
            int c = 0;
            for (int r = 0; r < KK; r++) {
                if (sgate[r] > 0.5f) {
                    g_adj[i * KK + c] = sel[r];
                    g_w[i * KK + c]   = 0.0625f * sgate[r];  // dinv_src*dinv_dst = 1/16 (deg==16)
                    c++;
                }
            }
            g_cnt[i] = c;
        }
    }
}

// ---------------------------------------------------------------------------
// Kernel 2: Y[b,i,:] = sum_j w_e * x[b,j,:]   (gather from SMEM-staged x)
// One block per (column-quarter, batch).
// ---------------------------------------------------------------------------
#define GATHER_SMEM_FLOATS (NN * 64 + NN * KK * 2 + NN)
#define GATHER_SMEM_BYTES  (GATHER_SMEM_FLOATS * 4)

__global__ __launch_bounds__(256)
void gather_kernel(const float* __restrict__ x)
{
    extern __shared__ float smem[];
    float* xs   = smem;                       // [256][64]
    int*   sadj = (int*)(xs + NN * 64);       // [256*16]
    float* sw   = (float*)(sadj + NN * KK);   // [256*16]
    int*   scnt = (int*)(sw + NN * KK);       // [256]

    const int qtr = blockIdx.x;               // column quarter (0..3)
    const int b   = blockIdx.y;               // batch
    const int t   = threadIdx.x;
    const int c4  = t & 15;                   // col quad within quarter (0..15)
    const int dl  = t >> 4;                   // dst lane (0..15)

    const float* xb = &x[(long)b * NN * TT + qtr * 64];

    #pragma unroll
    for (int it = 0; it < 16; it++) {
        int idx  = it * 256 + t;              // 0..4095 float4 slots
        int node = idx >> 4;
        int cc   = idx & 15;
        float4 v = *(const float4*)&xb[node * TT + cc * 4];
        *(float4*)&xs[node * 64 + cc * 4] = v;
    }
    #pragma unroll
    for (int it = 0; it < 16; it++) {
        int e = it * 256 + t;                 // 0..4095 edges
        sadj[e] = g_adj[e];
        sw[e]   = g_w[e];
    }
    scnt[t] = g_cnt[t];
    __syncthreads();

    float* Yb = &g_Y[(long)b * NN * TT + qtr * 64];

    #pragma unroll
    for (int q = 0; q < 16; q++) {            // 16 dst per thread
        const int ii = dl + q * 16;
        const int c  = scnt[ii];
        float4 acc = make_float4(0.f, 0.f, 0.f, 0.f);
        #pragma unroll
        for (int k = 0; k < KK; k++) {
            if (k < c) {
                int   j = sadj[ii * KK + k];
                float w = sw[ii * KK + k];
                float4 h = *(const float4*)&xs[j * 64 + c4 * 4];
                acc.x = fmaf(w, h.x, acc.x);
                acc.y = fmaf(w, h.y, acc.y);
                acc.z = fmaf(w, h.z, acc.z);
                acc.w = fmaf(w, h.w, acc.w);
            }
        }
        *(float4*)&Yb[ii * TT + c4 * 4] = acc;
    }
}

// ---------------------------------------------------------------------------
// Kernel 3: out = Y @ W + bias   (fp32, packed f32x2 FMA, double-buffered)
// Tile 64x128, K-chunk 16, 256 threads, 4x8 microtile per thread, occ 4:
// grid 512 CTAs all resident in ONE wave (148x4=592 slots) -> balanced,
// 8 warps/SMSP for latency hiding.
// A stored smem-duplicated as (a,a) u64 pairs -> no packing in inner loop.
// Split-fragment n-mapping (tx*4 and 64+tx*4): conflict-free B LDS.
// ---------------------------------------------------------------------------
__device__ __forceinline__ unsigned long long pk2(float lo, float hi) {
    unsigned long long r;
    asm("mov.b64 %0, {%1, %2};" : "=l"(r) : "f"(lo), "f"(hi));
    return r;
}
__device__ __forceinline__ void fma2(unsigned long long& d,
                                     unsigned long long a, unsigned long long b) {
    asm("fma.rn.f32x2 %0, %1, %2, %3;" : "=l"(d) : "l"(a), "l"(b), "l"(d));
}
__device__ __forceinline__ void upk2(unsigned long long v, float& lo, float& hi) {
    asm("mov.b64 {%0, %1}, %2;" : "=f"(lo), "=f"(hi) : "l"(v));
}

#define AD_STRIDE 66    // u64 stride per k-row (64 + 2 pad)
#define GB_STRIDE 136   // f32 stride per k-row (128 + 8 pad)

__global__ __launch_bounds__(256, 4)
void gemm_YW_kernel(const float* __restrict__ W,
                    const float* __restrict__ bias,
                    float* __restrict__ out)
{
    __shared__ unsigned long long Ad[2][16][AD_STRIDE];  // duplicated (a,a)
    __shared__ float              Bsh[2][16][GB_STRIDE];

    const int t   = threadIdx.x;
    const int tx  = t & 15;            // n direction (two 4-wide fragments)
    const int ty  = t >> 4;            // m direction (4 rows each)
    const int row0 = blockIdx.y * 64;
    const int n0   = blockIdx.x * 128;

    const float* Y = g_Y;

    // Global-load assignments: A 1 float4/thread, B 2 float4/thread
    const int am  = t >> 2,           ak  = t & 3;
    const int bk0 = t >> 5,           bc0 = t & 31;
    const int bk1 = (t + 256) >> 5,   bc1 = (t + 256) & 31;

    unsigned long long acc[4][4];
    #pragma unroll
    for (int m = 0; m < 4; m++)
        #pragma unroll
        for (int p = 0; p < 4; p++) acc[m][p] = 0ULL;

    // ---- prologue: load chunk 0 into buffer 0 ----
    float4 pa  = *(const float4*)&Y[(row0 + am) * TT + ak * 4];
    float4 pb0 = *(const float4*)&W[bk0 * TT + n0 + bc0 * 4];
    float4 pb1 = *(const float4*)&W[bk1 * TT + n0 + bc1 * 4];

    Ad[0][ak * 4 + 0][am] = pk2(pa.x, pa.x);
    Ad[0][ak * 4 + 1][am] = pk2(pa.y, pa.y);
    Ad[0][ak * 4 + 2][am] = pk2(pa.z, pa.z);
    Ad[0][ak * 4 + 3][am] = pk2(pa.w, pa.w);
    *(float4*)&Bsh[0][bk0][bc0 * 4] = pb0;
    *(float4*)&Bsh[0][bk1][bc1 * 4] = pb1;
    __syncthreads();

    int buf = 0;
    for (int k0 = 0; k0 < TT; k0 += 16) {
        const int kn = k0 + 16;
        const bool has_next = (kn < TT);

        if (has_next) {
            pa  = *(const float4*)&Y[(row0 + am) * TT + kn + ak * 4];
            pb0 = *(const float4*)&W[(kn + bk0) * TT + n0 + bc0 * 4];
            pb1 = *(const float4*)&W[(kn + bk1) * TT + n0 + bc1 * 4];
        }

        #pragma unroll
        for (int kk = 0; kk < 16; kk++) {
            // A: 4 broadcast LDS.64 (pre-duplicated pairs)
            unsigned long long a0 = Ad[buf][kk][ty * 4 + 0];
            unsigned long long a1 = Ad[buf][kk][ty * 4 + 1];
            unsigned long long a2 = Ad[buf][kk][ty * 4 + 2];
            unsigned long long a3 = Ad[buf][kk][ty * 4 + 3];
            // B: conflict-free u64-pair loads
            ulonglong2 bq0 = *(const ulonglong2*)&Bsh[buf][kk][tx * 4];
            ulonglong2 bq1 = *(const ulonglong2*)&Bsh[buf][kk][64 + tx * 4];
            fma2(acc[0][0], a0, bq0.x); fma2(acc[0][1], a0, bq0.y);
            fma2(acc[0][2], a0, bq1.x); fma2(acc[0][3], a0, bq1.y);
            fma2(acc[1][0], a1, bq0.x); fma2(acc[1][1], a1, bq0.y);
            fma2(acc[1][2], a1, bq1.x); fma2(acc[1][3], a1, bq1.y);
            fma2(acc[2][0], a2, bq0.x); fma2(acc[2][1], a2, bq0.y);
            fma2(acc[2][2], a2, bq1.x); fma2(acc[2][3], a2, bq1.y);
            fma2(acc[3][0], a3, bq0.x); fma2(acc[3][1], a3, bq0.y);
            fma2(acc[3][2], a3, bq1.x); fma2(acc[3][3], a3, bq1.y);
        }

        if (has_next) {
            const int nb = buf ^ 1;
            Ad[nb][ak * 4 + 0][am] = pk2(pa.x, pa.x);
            Ad[nb][ak * 4 + 1][am] = pk2(pa.y, pa.y);
            Ad[nb][ak * 4 + 2][am] = pk2(pa.z, pa.z);
            Ad[nb][ak * 4 + 3][am] = pk2(pa.w, pa.w);
            *(float4*)&Bsh[nb][bk0][bc0 * 4] = pb0;
            *(float4*)&Bsh[nb][bk1][bc1 * 4] = pb1;
        }
        __syncthreads();
        buf ^= 1;
    }

    // Epilogue: add bias, write directly to out (2x STG.128 per row)
    float bv[8];
    #pragma unroll
    for (int p = 0; p < 4; p++) {
        bv[p]     = bias[n0 + tx * 4 + p];
        bv[4 + p] = bias[n0 + 64 + tx * 4 + p];
    }

    #pragma unroll
    for (int m = 0; m < 4; m++) {
        int row = row0 + ty * 4 + m;
        float v[8];
        #pragma unroll
        for (int p = 0; p < 4; p++) {
            upk2(acc[m][p], v[p * 2], v[p * 2 + 1]);
        }
        #pragma unroll
        for (int p = 0; p < 8; p++) v[p] += bv[p];
        *(float4*)&out[row * TT + n0 + tx * 4]      = make_float4(v[0], v[1], v[2], v[3]);
        *(float4*)&out[row * TT + n0 + 64 + tx * 4] = make_float4(v[4], v[5], v[6], v[7]);
    }
}

// ---------------------------------------------------------------------------
extern "C" void kernel_launch(void* const* d_in, const int* in_sizes, int n_in,
                              void* d_out, int out_size)
{
    const float* x      = (const float*)d_in[0];   // [64,256,256]
    const float* emb    = (const float*)d_in[1];   // [256,64]
    const float* W      = (const float*)d_in[2];   // [256,256]
    const float* bias   = (const float*)d_in[3];   // [256]
    const float* logits = (const float*)d_in[4];   // [65536,2]
    const float* gumbel = (const float*)d_in[5];   // [65536,2]
    float* out = (float*)d_out;

    // Host-side attribute sets (non-stream API: capture-safe, deterministic)
    cudaFuncSetAttribute(prep_emb_kernel,
                         cudaFuncAttributeMaxDynamicSharedMemorySize,
                         PREP_SMEM_BYTES);
    cudaFuncSetAttribute(gather_kernel,
                         cudaFuncAttributeMaxDynamicSharedMemorySize,
                         GATHER_SMEM_BYTES);

    prep_emb_kernel<<<1, 256, PREP_SMEM_BYTES>>>(emb);
    build_graph_kernel<<<NN, 256>>>(emb, logits, gumbel);
    gather_kernel<<<dim3(4, NB), 256, GATHER_SMEM_BYTES>>>(x);
    gemm_YW_kernel<<<dim3(2, 256), 256>>>(W, bias, out);
}